// round 11
// baseline (speedup 1.0000x reference)
#include <cuda_runtime.h>
#include <math.h>

#define ND 10000
#define NG 30000
#define HDIM 128
#define EDG 150000
#define EGD 150000
#define EGG 300000

typedef unsigned long long ull;

// ---------------- scratch (device globals; no allocation) ----------------
__device__ float g_kqv_d[ND * 384];
__device__ float g_kqv_g[NG * 384];
__device__ float g_qt_d[ND * HDIM];
__device__ float g_qt_g0[NG * HDIM];
__device__ float g_qt_g2[NG * HDIM];
__device__ float g_agg_d[ND * HDIM];
__device__ float g_agg_g[NG * HDIM];
__device__ float g_x_d[ND * HDIM];
__device__ float g_x_g[NG * HDIM];
__device__ int g_cnt_g[NG + 1];
__device__ int g_off_g[NG + 1];
__device__ int g_cur_g[NG];
__device__ int g_list_g[EDG + EGG];
__device__ int g_cnt_d[ND + 1];
__device__ int g_off_d[ND + 1];
__device__ int g_cur_d[ND];
__device__ int g_list_d[EGD];

// ---------------- helpers ----------------
__device__ __forceinline__ float gelu_t(float x) {
    float u = 0.7978845608028654f * (x + 0.044715f * x * x * x);
    return 0.5f * x * (1.0f + tanhf(u));
}
__device__ __forceinline__ ull pack2(float lo, float hi) {
    ull r;
    asm("mov.b64 %0, {%1, %2};" : "=l"(r) : "f"(lo), "f"(hi));
    return r;
}
__device__ __forceinline__ void fma2(ull &acc, ull a, ull b) {
    asm("fma.rn.f32x2 %0, %1, %2, %0;" : "+l"(acc) : "l"(a), "l"(b));
}
__device__ __forceinline__ void unpack2(ull v, float &lo, float &hi) {
    asm("mov.b64 {%0, %1}, %2;" : "=f"(lo), "=f"(hi) : "l"(v));
}

// ---------------- CSR build (merged) ----------------
__global__ void hist_all(const int* __restrict__ dst_dg, const int* __restrict__ dst_gg,
                         const int* __restrict__ dst_gd, int* cnt_g, int* cnt_d) {
    const int NTOT = EDG + EGG + EGD;
    for (int i = blockIdx.x * blockDim.x + threadIdx.x; i < NTOT; i += gridDim.x * blockDim.x) {
        if (i < EDG) atomicAdd(&cnt_g[dst_dg[i]], 1);
        else if (i < EDG + EGG) atomicAdd(&cnt_g[dst_gg[i - EDG]], 1);
        else atomicAdd(&cnt_d[dst_gd[i - EDG - EGG]], 1);
    }
}

// block 0 scans (cnt_g -> off_g, NG); block 1 scans (cnt_d -> off_d, ND)
__global__ void scan2_kernel(const int* __restrict__ cnt_g, int* __restrict__ off_g,
                             const int* __restrict__ cnt_d, int* __restrict__ off_d) {
    const int* cnt = blockIdx.x == 0 ? cnt_g : cnt_d;
    int* off = blockIdx.x == 0 ? off_g : off_d;
    int n = blockIdx.x == 0 ? NG : ND;
    __shared__ int part[1024];
    int t = threadIdx.x;
    int chunk = (n + 1023) / 1024;
    int b = t * chunk, e = b + chunk;
    if (e > n) e = n;
    if (b > n) b = n;
    int s = 0;
    for (int i = b; i < e; i++) s += cnt[i];
    part[t] = s;
    __syncthreads();
    for (int d = 1; d < 1024; d <<= 1) {
        int v = 0;
        if (t >= d) v = part[t - d];
        __syncthreads();
        part[t] += v;
        __syncthreads();
    }
    int run = (t == 0) ? 0 : part[t - 1];
    for (int i = b; i < e; i++) { off[i] = run; run += cnt[i]; }
    if (t == 1023) off[n] = part[1023];
}

__global__ void fill_all(const int* __restrict__ src_dg, const int* __restrict__ dst_dg,
                         const int* __restrict__ src_gg, const int* __restrict__ dst_gg,
                         const int* __restrict__ src_gd, const int* __restrict__ dst_gd,
                         const int* __restrict__ off_g, int* cur_g, int* list_g,
                         const int* __restrict__ off_d, int* cur_d, int* list_d) {
    const int NTOT = EDG + EGG + EGD;
    for (int i = blockIdx.x * blockDim.x + threadIdx.x; i < NTOT; i += gridDim.x * blockDim.x) {
        if (i < EDG) {
            int d = dst_dg[i];
            int pos = off_g[d] + atomicAdd(&cur_g[d], 1);
            list_g[pos] = (src_dg[i] << 1);
        } else if (i < EDG + EGG) {
            int j = i - EDG;
            int d = dst_gg[j];
            int pos = off_g[d] + atomicAdd(&cur_g[d], 1);
            list_g[pos] = (src_gg[j] << 1) | 1;
        } else {
            int j = i - EDG - EGG;
            int d = dst_gd[j];
            int pos = off_d[d] + atomicAdd(&cur_d[d], 1);
            list_d[pos] = (src_gd[j] << 1);
        }
    }
}

__global__ void sort_all(const int* __restrict__ off_g, int* list_g,
                         const int* __restrict__ off_d, int* list_d) {
    int node = blockIdx.x * blockDim.x + threadIdx.x;
    const int* off;
    int* list;
    if (node < NG) { off = off_g; list = list_g; }
    else if (node < NG + ND) { off = off_d; list = list_d; node -= NG; }
    else return;
    int b = off[node], e = off[node + 1];
    for (int i = b + 1; i < e; i++) {
        int v = list[i];
        int j = i - 1;
        while (j >= b && list[j] > v) { list[j + 1] = list[j]; j--; }
        list[j + 1] = v;
    }
}

// ---------------- GEMM 128x128 tile, K=128, 8x8 register blocking, f32x2 ----------------
// MODE 0: C = A@W + b
// MODE 1: C = g*(gelu(A)@W + b) + (1-g)*xold,  g = sigmoid(skip)
template <int MODE>
__global__ __launch_bounds__(256) void gemm_big(
    const float* __restrict__ A, const float* __restrict__ W,
    const float* __restrict__ bias, const float* __restrict__ xold,
    const float* __restrict__ skipp, float* __restrict__ C, int M, int N)
{
    __shared__ __align__(16) float As[2][8 * 136];
    __shared__ __align__(16) float Bs[2][8 * 128];
    const int tid = threadIdx.x;
    const int m0 = blockIdx.y * 128, n0 = blockIdx.x * 128;
    const int tx = tid & 15, ty = tid >> 4;

    // global load mapping
    const int lm = tid >> 1;             // A row within tile (0..127)
    const int lk = (tid & 1) << 2;       // A col sub-chunk (0 or 4)
    const int bk = tid >> 5;             // B row within chunk (0..7)
    const int bn = (tid & 31) << 2;      // B col (0..124)
    const int arow = m0 + lm;
    const bool avalid = (arow < M);
    const float* Aptr = A + (long)arow * 128 + lk;
    const float* Wptr = W + (long)bk * N + n0 + bn;

    ull acc[8][4];
#pragma unroll
    for (int i = 0; i < 8; i++)
#pragma unroll
        for (int j = 0; j < 4; j++) acc[i][j] = 0ull;

    float4 ag, bg;
    // prologue: load+store chunk 0
    ag = avalid ? *(const float4*)Aptr : make_float4(0.f, 0.f, 0.f, 0.f);
    if (MODE == 1) { ag.x = gelu_t(ag.x); ag.y = gelu_t(ag.y); ag.z = gelu_t(ag.z); ag.w = gelu_t(ag.w); }
    bg = *(const float4*)Wptr;
    As[0][(lk + 0) * 136 + lm] = ag.x;
    As[0][(lk + 1) * 136 + lm] = ag.y;
    As[0][(lk + 2) * 136 + lm] = ag.z;
    As[0][(lk + 3) * 136 + lm] = ag.w;
    *(float4*)&Bs[0][bk * 128 + bn] = bg;
    __syncthreads();

    for (int c = 0; c < 16; ++c) {
        const int buf = c & 1;
        if (c < 15) {
            const int k0 = (c + 1) * 8;
            ag = avalid ? *(const float4*)(Aptr + k0) : make_float4(0.f, 0.f, 0.f, 0.f);
            if (MODE == 1) { ag.x = gelu_t(ag.x); ag.y = gelu_t(ag.y); ag.z = gelu_t(ag.z); ag.w = gelu_t(ag.w); }
            bg = *(const float4*)(Wptr + (long)k0 * N);
        }
#pragma unroll
        for (int kk = 0; kk < 8; kk++) {
            const float* as = &As[buf][kk * 136];
            float4 a0 = *(const float4*)(as + (ty << 2));
            float4 a1 = *(const float4*)(as + 64 + (ty << 2));
            const float* bs = &Bs[buf][kk * 128];
            ulonglong2 b0 = *(const ulonglong2*)(bs + (tx << 2));
            ulonglong2 b1 = *(const ulonglong2*)(bs + 64 + (tx << 2));
            ull bb0 = b0.x, bb1 = b0.y, bb2 = b1.x, bb3 = b1.y;
            float av[8] = {a0.x, a0.y, a0.z, a0.w, a1.x, a1.y, a1.z, a1.w};
#pragma unroll
            for (int i = 0; i < 8; i++) {
                ull s = pack2(av[i], av[i]);
                fma2(acc[i][0], s, bb0);
                fma2(acc[i][1], s, bb1);
                fma2(acc[i][2], s, bb2);
                fma2(acc[i][3], s, bb3);
            }
        }
        if (c < 15) {
            __syncthreads();
            const int nb = buf ^ 1;
            As[nb][(lk + 0) * 136 + lm] = ag.x;
            As[nb][(lk + 1) * 136 + lm] = ag.y;
            As[nb][(lk + 2) * 136 + lm] = ag.z;
            As[nb][(lk + 3) * 136 + lm] = ag.w;
            *(float4*)&Bs[nb][bk * 128 + bn] = bg;
            __syncthreads();
        }
    }

    float gate = 0.f, gate1 = 0.f;
    if (MODE == 1) {
        gate = 1.f / (1.f + __expf(-skipp[0]));
        gate1 = 1.f - gate;
    }
#pragma unroll
    for (int i = 0; i < 8; i++) {
        const int row = m0 + ((i < 4) ? ((ty << 2) + i) : (64 + (ty << 2) + i - 4));
        if (row >= M) continue;
#pragma unroll
        for (int half = 0; half < 2; half++) {
            const int col = n0 + half * 64 + (tx << 2);
            float c0, c1, c2, c3;
            unpack2(acc[i][half * 2 + 0], c0, c1);
            unpack2(acc[i][half * 2 + 1], c2, c3);
            float o0 = c0 + bias[col + 0];
            float o1 = c1 + bias[col + 1];
            float o2 = c2 + bias[col + 2];
            float o3 = c3 + bias[col + 3];
            float* Cp = C + (long)row * N + col;
            if (MODE == 0) {
                Cp[0] = o0; Cp[1] = o1; Cp[2] = o2; Cp[3] = o3;
            } else {
                const float* xo = xold + (long)row * N + col;
                Cp[0] = gate * o0 + gate1 * xo[0];
                Cp[1] = gate * o1 + gate1 * xo[1];
                Cp[2] = gate * o2 + gate1 * xo[2];
                Cp[3] = gate * o3 + gate1 * xo[3];
            }
        }
    }
}

// ---------------- q-tilde: qt[n,h,d] = (sum_f q[n,h,f]*arel[h,d,f]) * prel[h] * scale ----------
// blockIdx.y selects edge-type config: 0 -> (g, et0), 1 -> (g, et2), 2 -> (d, et1)
__global__ __launch_bounds__(128) void qt_kernel(
    const float* __restrict__ kqv_g, const float* __restrict__ kqv_d,
    const float* __restrict__ arel_l, const float* __restrict__ prel_l, float scale,
    float* __restrict__ qt_g0, float* __restrict__ qt_g2, float* __restrict__ qt_d)
{
    const float* kqv;
    const float* arel;
    const float* prel;
    float* qt;
    int Nn;
    if (blockIdx.y == 0)      { kqv = kqv_g; arel = arel_l;            prel = prel_l;     qt = qt_g0; Nn = NG; }
    else if (blockIdx.y == 1) { kqv = kqv_g; arel = arel_l + 2 * 4096; prel = prel_l + 8; qt = qt_g2; Nn = NG; }
    else                      { kqv = kqv_d; arel = arel_l + 1 * 4096; prel = prel_l + 4; qt = qt_d;  Nn = ND; }

    __shared__ float arelT[32][128]; // [f][h*32+d]
    __shared__ float qsh[128];
    const int t = threadIdx.x; // t = h*32+d
    for (int i = t; i < 4096; i += 128) {
        int h = i >> 10, rem = i & 1023;
        int d = rem >> 5, f = rem & 31;
        arelT[f][(h << 5) + d] = arel[i];
    }
    const int h = t >> 5;
    const float pr = prel[h] * scale;
    __syncthreads();
    for (int node = blockIdx.x; node < Nn; node += gridDim.x) {
        qsh[t] = kqv[(long)node * 384 + 128 + t]; // q block
        __syncthreads();
        float s = 0.f;
        const float* qh = &qsh[h << 5];
#pragma unroll
        for (int f = 0; f < 32; f++) s += qh[f] * arelT[f][t];
        qt[(long)node * 128 + t] = s * pr;
        __syncthreads();
    }
}

// ---------------- aggregation: warp per dst node, online softmax over incoming edges ----------
__global__ __launch_bounds__(256) void agg_kernel(
    const float* __restrict__ kqv0, const float* __restrict__ kqv1,
    const float* __restrict__ qt0t, const float* __restrict__ qt1t,
    const float* __restrict__ mrel0g, const float* __restrict__ mrel1g,
    const int* __restrict__ off, const int* __restrict__ list,
    float* __restrict__ agg, int Ndst, int two_types)
{
    __shared__ float mr0[4096];
    __shared__ float mr1[4096];
    __shared__ __align__(16) float Ssh[8][128];
    const int tid = threadIdx.x;
    for (int i = tid; i < 4096; i += 256) {
        mr0[i] = mrel0g[i];
        mr1[i] = mrel1g[i];
    }
    __syncthreads();
    const int warp = tid >> 5, lane = tid & 31;
    const int h = lane >> 3, f0 = (lane & 7) << 2;

    for (int node = blockIdx.x * 8 + warp; node < Ndst; node += gridDim.x * 8) {
        float4 q0 = ((const float4*)(qt0t + (long)node * 128))[lane];
        float4 q1 = make_float4(0.f, 0.f, 0.f, 0.f);
        if (two_types) q1 = ((const float4*)(qt1t + (long)node * 128))[lane];
        float m = -1e30f, lsum = 0.f;
        float4 S0 = make_float4(0.f, 0.f, 0.f, 0.f);
        float4 S1 = make_float4(0.f, 0.f, 0.f, 0.f);
        const int b = off[node], e = off[node + 1];
        for (int i = b; i < e; i++) {
            const int ent = list[i];
            const int tb = ent & 1;
            const float4* base = (const float4*)((tb ? kqv1 : kqv0) + (long)(ent >> 1) * 384);
            float4 k4 = base[lane];       // k block
            float4 qr = tb ? q1 : q0;
            float p = k4.x * qr.x + k4.y * qr.y + k4.z * qr.z + k4.w * qr.w;
            p += __shfl_xor_sync(0xffffffffu, p, 1);
            p += __shfl_xor_sync(0xffffffffu, p, 2);
            p += __shfl_xor_sync(0xffffffffu, p, 4);
            float mn = fmaxf(m, p);
            float c = __expf(m - mn);
            float ex = __expf(p - mn);
            m = mn;
            lsum = lsum * c + ex;
            float4 v4 = base[64 + lane];  // v block
            S0.x *= c; S0.y *= c; S0.z *= c; S0.w *= c;
            S1.x *= c; S1.y *= c; S1.z *= c; S1.w *= c;
            if (tb) { S1.x += ex * v4.x; S1.y += ex * v4.y; S1.z += ex * v4.z; S1.w += ex * v4.w; }
            else    { S0.x += ex * v4.x; S0.y += ex * v4.y; S0.z += ex * v4.z; S0.w += ex * v4.w; }
        }
        float inv = lsum > 0.f ? 1.f / lsum : 0.f;
        float4 o = make_float4(0.f, 0.f, 0.f, 0.f);
        ((float4*)Ssh[warp])[lane] = S0;
        __syncwarp();
        {
            const float* Sh = &Ssh[warp][h << 5];
            const float* Mm = &mr0[h << 10];
#pragma unroll
            for (int d = 0; d < 32; d++) {
                float s = Sh[d];
                const float* mp = Mm + (d << 5) + f0;
                o.x += s * mp[0]; o.y += s * mp[1]; o.z += s * mp[2]; o.w += s * mp[3];
            }
        }
        if (two_types) {
            __syncwarp();
            ((float4*)Ssh[warp])[lane] = S1;
            __syncwarp();
            const float* Sh = &Ssh[warp][h << 5];
            const float* Mm = &mr1[h << 10];
#pragma unroll
            for (int d = 0; d < 32; d++) {
                float s = Sh[d];
                const float* mp = Mm + (d << 5) + f0;
                o.x += s * mp[0]; o.y += s * mp[1]; o.z += s * mp[2]; o.w += s * mp[3];
            }
        }
        o.x *= inv; o.y *= inv; o.z *= inv; o.w *= inv;
        ((float4*)(agg + (long)node * 128))[lane] = o;
    }
}

// ---------------- host ----------------
extern "C" void kernel_launch(void* const* d_in, const int* in_sizes, int n_in,
                              void* d_out, int out_size) {
    const float* x_d    = (const float*)d_in[0];
    const float* x_g    = (const float*)d_in[1];
    const int*   src_dg = (const int*)d_in[2];
    const int*   dst_dg = (const int*)d_in[3];
    const int*   src_gd = (const int*)d_in[4];
    const int*   dst_gd = (const int*)d_in[5];
    const int*   src_gg = (const int*)d_in[6];
    const int*   dst_gg = (const int*)d_in[7];
    const float* Wkqv_d = (const float*)d_in[8];
    const float* bkqv_d = (const float*)d_in[9];
    const float* Wkqv_g = (const float*)d_in[10];
    const float* bkqv_g = (const float*)d_in[11];
    const float* Wout_d = (const float*)d_in[12];
    const float* bout_d = (const float*)d_in[13];
    const float* Wout_g = (const float*)d_in[14];
    const float* bout_g = (const float*)d_in[15];
    const float* skip_d = (const float*)d_in[16];
    const float* skip_g = (const float*)d_in[17];
    const float* arel   = (const float*)d_in[18];
    const float* mrel   = (const float*)d_in[19];
    const float* prel   = (const float*)d_in[20];

    float *kqv_d, *kqv_g, *qt_d, *qt_g0, *qt_g2, *agg_d, *agg_g, *xbuf_d, *xbuf_g;
    int *cnt_g, *off_g, *cur_g, *list_g, *cnt_d, *off_d, *cur_d, *list_d;
    cudaGetSymbolAddress((void**)&kqv_d, g_kqv_d);
    cudaGetSymbolAddress((void**)&kqv_g, g_kqv_g);
    cudaGetSymbolAddress((void**)&qt_d, g_qt_d);
    cudaGetSymbolAddress((void**)&qt_g0, g_qt_g0);
    cudaGetSymbolAddress((void**)&qt_g2, g_qt_g2);
    cudaGetSymbolAddress((void**)&agg_d, g_agg_d);
    cudaGetSymbolAddress((void**)&agg_g, g_agg_g);
    cudaGetSymbolAddress((void**)&xbuf_d, g_x_d);
    cudaGetSymbolAddress((void**)&xbuf_g, g_x_g);
    cudaGetSymbolAddress((void**)&cnt_g, g_cnt_g);
    cudaGetSymbolAddress((void**)&off_g, g_off_g);
    cudaGetSymbolAddress((void**)&cur_g, g_cur_g);
    cudaGetSymbolAddress((void**)&list_g, g_list_g);
    cudaGetSymbolAddress((void**)&cnt_d, g_cnt_d);
    cudaGetSymbolAddress((void**)&off_d, g_off_d);
    cudaGetSymbolAddress((void**)&cur_d, g_cur_d);
    cudaGetSymbolAddress((void**)&list_d, g_list_d);

    // ---- CSR build (edges identical across layers) ----
    cudaMemsetAsync(cnt_g, 0, sizeof(int) * NG);
    cudaMemsetAsync(cnt_d, 0, sizeof(int) * ND);
    hist_all<<<512, 256>>>(dst_dg, dst_gg, dst_gd, cnt_g, cnt_d);
    scan2_kernel<<<2, 1024>>>(cnt_g, off_g, cnt_d, off_d);
    cudaMemsetAsync(cur_g, 0, sizeof(int) * NG);
    cudaMemsetAsync(cur_d, 0, sizeof(int) * ND);
    fill_all<<<512, 256>>>(src_dg, dst_dg, src_gg, dst_gg, src_gd, dst_gd,
                           off_g, cur_g, list_g, off_d, cur_d, list_d);
    sort_all<<<(NG + ND + 255) / 256, 256>>>(off_g, list_g, off_d, list_d);

    const float SCALE = 0.1767766952966369f; // 1/sqrt(32)
    const float* xd = x_d;
    const float* xg = x_g;
    for (int l = 0; l < 2; l++) {
        // fused K/Q/V projections
        gemm_big<0><<<dim3(3, (ND + 127) / 128), 256>>>(
            xd, Wkqv_d + l * 128 * 384, bkqv_d + l * 384, nullptr, nullptr, kqv_d, ND, 384);
        gemm_big<0><<<dim3(3, (NG + 127) / 128), 256>>>(
            xg, Wkqv_g + l * 128 * 384, bkqv_g + l * 384, nullptr, nullptr, kqv_g, NG, 384);
        // dst-side q-tilde per (dst node, edge type): y=0 (g,et0), y=1 (g,et2), y=2 (d,et1)
        qt_kernel<<<dim3(512, 3), 128>>>(kqv_g, kqv_d, arel + l * 3 * 4096, prel + l * 12,
                                         SCALE, qt_g0, qt_g2, qt_d);
        // edge aggregation with joint segment softmax
        agg_kernel<<<(NG + 7) / 8, 256>>>(
            kqv_d, kqv_g, qt_g0, qt_g2,
            mrel + (l * 3 + 0) * 4096, mrel + (l * 3 + 2) * 4096,
            off_g, list_g, agg_g, NG, 1);
        agg_kernel<<<(ND + 7) / 8, 256>>>(
            kqv_g, kqv_g, qt_d, qt_d,
            mrel + (l * 3 + 1) * 4096, mrel + (l * 3 + 1) * 4096,
            off_d, list_d, agg_d, ND, 0);
        // output projection + gated skip
        float* od = (l == 1) ? (float*)d_out : xbuf_d;
        float* og = (l == 1) ? ((float*)d_out) + ND * HDIM : xbuf_g;
        gemm_big<1><<<dim3(1, (ND + 127) / 128), 256>>>(
            agg_d, Wout_d + l * 128 * 128, bout_d + l * 128, xd, skip_d + l, od, ND, 128);
        gemm_big<1><<<dim3(1, (NG + 127) / 128), 256>>>(
            agg_g, Wout_g + l * 128 * 128, bout_g + l * 128, xg, skip_g + l, og, NG, 128);
        xd = od;
        xg = og;
    }
}

// round 12
// speedup vs baseline: 1.2066x; 1.2066x over previous
#include <cuda_runtime.h>
#include <math.h>
#include <stdint.h>

#define ND 10000
#define NG 30000
#define HDIM 128
#define EDG 150000
#define EGD 150000
#define EGG 300000

// ---------------- scratch (device globals; no allocation) ----------------
__device__ float g_kqv_d[ND * 384];
__device__ float g_kqv_g[NG * 384];
__device__ float g_qt_d[ND * HDIM];
__device__ float g_qt_g0[NG * HDIM];
__device__ float g_qt_g2[NG * HDIM];
__device__ float g_agg_d[ND * HDIM];
__device__ float g_agg_g[NG * HDIM];
__device__ float g_x_d[ND * HDIM];
__device__ float g_x_g[NG * HDIM];
__device__ __align__(16) int g_cnt_g[NG + 1];
__device__ __align__(16) int g_off_g[NG + 1];
__device__ int g_cur_g[NG];
__device__ int g_list_g[EDG + EGG];
__device__ __align__(16) int g_cnt_d[ND + 1];
__device__ __align__(16) int g_off_d[ND + 1];
__device__ int g_cur_d[ND];
__device__ int g_list_d[EGD];

// ---------------- helpers ----------------
__device__ __forceinline__ float gelu_t(float x) {
    float u = 0.7978845608028654f * (x + 0.044715f * x * x * x);
    return 0.5f * x * (1.0f + tanhf(u));
}
__device__ __forceinline__ uint32_t f2tf32(float x) {
    uint32_t u;
    asm("cvt.rna.tf32.f32 %0, %1;" : "=r"(u) : "f"(x));
    return u;
}
__device__ __forceinline__ void mma_tf32(float* c, const uint32_t* a, uint32_t b0, uint32_t b1) {
    asm volatile(
        "mma.sync.aligned.m16n8k8.row.col.f32.tf32.tf32.f32 "
        "{%0,%1,%2,%3}, {%4,%5,%6,%7}, {%8,%9}, {%0,%1,%2,%3};"
        : "+f"(c[0]), "+f"(c[1]), "+f"(c[2]), "+f"(c[3])
        : "r"(a[0]), "r"(a[1]), "r"(a[2]), "r"(a[3]), "r"(b0), "r"(b1));
}

// ---------------- CSR build ----------------
__global__ void hist_all(const int* __restrict__ dst_dg, const int* __restrict__ dst_gg,
                         const int* __restrict__ dst_gd, int* cnt_g, int* cnt_d) {
    const int NTOT = EDG + EGG + EGD;
    for (int i = blockIdx.x * blockDim.x + threadIdx.x; i < NTOT; i += gridDim.x * blockDim.x) {
        if (i < EDG) atomicAdd(&cnt_g[dst_dg[i]], 1);
        else if (i < EDG + EGG) atomicAdd(&cnt_g[dst_gg[i - EDG]], 1);
        else atomicAdd(&cnt_d[dst_gd[i - EDG - EGG]], 1);
    }
}

// block 0: cnt_g -> off_g (NG); block 1: cnt_d -> off_d (ND). chunk=32, int4 loads.
__global__ void scan2_kernel(const int* __restrict__ cnt_g, int* __restrict__ off_g,
                             const int* __restrict__ cnt_d, int* __restrict__ off_d) {
    const int* cnt = blockIdx.x == 0 ? cnt_g : cnt_d;
    int* off = blockIdx.x == 0 ? off_g : off_d;
    const int n = blockIdx.x == 0 ? NG : ND;
    __shared__ int part[1024];
    const int t = threadIdx.x;
    const int b = t * 32;
    int s = 0;
    if (b + 32 <= n) {
        const int4* p = (const int4*)(cnt + b);
#pragma unroll
        for (int i = 0; i < 8; i++) { int4 v = p[i]; s += v.x + v.y + v.z + v.w; }
    } else {
        for (int i = b; i < n; i++) s += cnt[i];
    }
    part[t] = s;
    __syncthreads();
    for (int d = 1; d < 1024; d <<= 1) {
        int v = 0;
        if (t >= d) v = part[t - d];
        __syncthreads();
        part[t] += v;
        __syncthreads();
    }
    int run = (t == 0) ? 0 : part[t - 1];
    int e = b + 32 < n ? b + 32 : n;
    for (int i = b; i < e; i++) { off[i] = run; run += cnt[i]; }
    if (b <= n && e == n) off[n] = run;
}

__global__ void fill_all(const int* __restrict__ src_dg, const int* __restrict__ dst_dg,
                         const int* __restrict__ src_gg, const int* __restrict__ dst_gg,
                         const int* __restrict__ src_gd, const int* __restrict__ dst_gd,
                         const int* __restrict__ off_g, int* cur_g, int* list_g,
                         const int* __restrict__ off_d, int* cur_d, int* list_d) {
    const int NTOT = EDG + EGG + EGD;
    for (int i = blockIdx.x * blockDim.x + threadIdx.x; i < NTOT; i += gridDim.x * blockDim.x) {
        if (i < EDG) {
            int d = dst_dg[i];
            int pos = off_g[d] + atomicAdd(&cur_g[d], 1);
            list_g[pos] = (src_dg[i] << 1);
        } else if (i < EDG + EGG) {
            int j = i - EDG;
            int d = dst_gg[j];
            int pos = off_g[d] + atomicAdd(&cur_g[d], 1);
            list_g[pos] = (src_gg[j] << 1) | 1;
        } else {
            int j = i - EDG - EGG;
            int d = dst_gd[j];
            int pos = off_d[d] + atomicAdd(&cur_d[d], 1);
            list_d[pos] = (src_gd[j] << 1);
        }
    }
}

// per-node insertion sort, segment staged in shared memory (strided: no bank conflicts)
#define SORT_CAP 48
__global__ __launch_bounds__(256) void sort_all(const int* __restrict__ off_g, int* list_g,
                                                const int* __restrict__ off_d, int* list_d) {
    __shared__ int sbuf[SORT_CAP * 256];
    int node = blockIdx.x * blockDim.x + threadIdx.x;
    const int t = threadIdx.x;
    const int* off;
    int* list;
    if (node < NG) { off = off_g; list = list_g; }
    else if (node < NG + ND) { off = off_d; list = list_d; node -= NG; }
    else return;
    const int b = off[node], e = off[node + 1];
    const int deg = e - b;
    if (deg <= 1) return;
    if (deg <= SORT_CAP) {
        for (int j = 0; j < deg; j++) sbuf[j * 256 + t] = list[b + j];
        for (int i = 1; i < deg; i++) {
            int v = sbuf[i * 256 + t];
            int j = i - 1;
            while (j >= 0 && sbuf[j * 256 + t] > v) { sbuf[(j + 1) * 256 + t] = sbuf[j * 256 + t]; j--; }
            sbuf[(j + 1) * 256 + t] = v;
        }
        for (int j = 0; j < deg; j++) list[b + j] = sbuf[j * 256 + t];
    } else {
        for (int i = b + 1; i < e; i++) {
            int v = list[i];
            int j = i - 1;
            while (j >= b && list[j] > v) { list[j + 1] = list[j]; j--; }
            list[j + 1] = v;
        }
    }
}

// ---------------- tensor-core GEMM: 128x128 tile, K=128, tf32 mma.sync ----------------
// Handles TWO independent problems in one grid (split on blockIdx.y).
// MODE 0: C = A@W + b
// MODE 1: C = g*(gelu(A)@W + b) + (1-g)*xold,  g = sigmoid(skip)
template <int MODE>
__global__ __launch_bounds__(256) void gemm_tc(
    const float* __restrict__ A0, const float* __restrict__ W0, const float* __restrict__ bias0,
    const float* __restrict__ x0, const float* __restrict__ s0, float* __restrict__ C0, int M0,
    const float* __restrict__ A1, const float* __restrict__ W1, const float* __restrict__ bias1,
    const float* __restrict__ x1, const float* __restrict__ s1, float* __restrict__ C1, int M1,
    int nby0, int N)
{
    __shared__ __align__(16) float As[2][8][136];  // [k][m]
    __shared__ __align__(16) float Bs[2][8][136];  // [k][n]
    const float *A, *W, *bias, *xold, *skipp;
    float* C;
    int M;
    int by = blockIdx.y;
    if (by < nby0) { A = A0; W = W0; bias = bias0; xold = x0; skipp = s0; C = C0; M = M0; }
    else { by -= nby0; A = A1; W = W1; bias = bias1; xold = x1; skipp = s1; C = C1; M = M1; }

    const int tid = threadIdx.x;
    const int m0 = by * 128, n0 = blockIdx.x * 128;
    const int wid = tid >> 5, lane = tid & 31;
    const int wm = wid & 3, wn = wid >> 2;      // warp tile: 32(m) x 64(n)
    const int lr = lane >> 2, lc = lane & 3;

    // global load mapping
    const int lm = tid >> 1, lk = (tid & 1) << 2;   // A: row, k-sub
    const int bkr = tid >> 5, bn = (tid & 31) << 2; // B: k-row, col
    const int arow = m0 + lm;
    const bool avalid = arow < M;
    const float* Aptr = A + (long)arow * 128 + lk;
    const float* Wptr = W + (long)bkr * N + n0 + bn;

    float acc[2][8][4];
#pragma unroll
    for (int i = 0; i < 2; i++)
#pragma unroll
        for (int j = 0; j < 8; j++)
#pragma unroll
            for (int q = 0; q < 4; q++) acc[i][j][q] = 0.f;

    uint32_t agv[4], bgv[4];
    {   // prologue chunk 0
        float4 av = avalid ? *(const float4*)Aptr : make_float4(0.f, 0.f, 0.f, 0.f);
        if (MODE == 1) { av.x = gelu_t(av.x); av.y = gelu_t(av.y); av.z = gelu_t(av.z); av.w = gelu_t(av.w); }
        agv[0] = f2tf32(av.x); agv[1] = f2tf32(av.y); agv[2] = f2tf32(av.z); agv[3] = f2tf32(av.w);
        float4 bv = *(const float4*)Wptr;
        bgv[0] = f2tf32(bv.x); bgv[1] = f2tf32(bv.y); bgv[2] = f2tf32(bv.z); bgv[3] = f2tf32(bv.w);
        As[0][lk + 0][lm] = __uint_as_float(agv[0]);
        As[0][lk + 1][lm] = __uint_as_float(agv[1]);
        As[0][lk + 2][lm] = __uint_as_float(agv[2]);
        As[0][lk + 3][lm] = __uint_as_float(agv[3]);
        float4 bs4;
        bs4.x = __uint_as_float(bgv[0]); bs4.y = __uint_as_float(bgv[1]);
        bs4.z = __uint_as_float(bgv[2]); bs4.w = __uint_as_float(bgv[3]);
        *(float4*)&Bs[0][bkr][bn] = bs4;
    }
    __syncthreads();

    for (int c = 0; c < 16; ++c) {
        const int buf = c & 1;
        if (c < 15) {
            const int k0 = (c + 1) * 8;
            float4 av = avalid ? *(const float4*)(Aptr + k0) : make_float4(0.f, 0.f, 0.f, 0.f);
            if (MODE == 1) { av.x = gelu_t(av.x); av.y = gelu_t(av.y); av.z = gelu_t(av.z); av.w = gelu_t(av.w); }
            agv[0] = f2tf32(av.x); agv[1] = f2tf32(av.y); agv[2] = f2tf32(av.z); agv[3] = f2tf32(av.w);
            float4 bv = *(const float4*)(Wptr + (long)k0 * N);
            bgv[0] = f2tf32(bv.x); bgv[1] = f2tf32(bv.y); bgv[2] = f2tf32(bv.z); bgv[3] = f2tf32(bv.w);
        }
        // fragments + mma for this k8 slice
        uint32_t af[2][4];
        const int mb = wm * 32;
#pragma unroll
        for (int mt = 0; mt < 2; mt++) {
            const int mo = mb + mt * 16 + lr;
            af[mt][0] = __float_as_uint(As[buf][lc][mo]);
            af[mt][1] = __float_as_uint(As[buf][lc][mo + 8]);
            af[mt][2] = __float_as_uint(As[buf][lc + 4][mo]);
            af[mt][3] = __float_as_uint(As[buf][lc + 4][mo + 8]);
        }
#pragma unroll
        for (int nt = 0; nt < 8; nt++) {
            const int nb2 = wn * 64 + nt * 8 + lr;
            uint32_t b0 = __float_as_uint(Bs[buf][lc][nb2]);
            uint32_t b1 = __float_as_uint(Bs[buf][lc + 4][nb2]);
            mma_tf32(acc[0][nt], af[0], b0, b1);
            mma_tf32(acc[1][nt], af[1], b0, b1);
        }
        if (c < 15) {
            __syncthreads();
            const int nb = buf ^ 1;
            As[nb][lk + 0][lm] = __uint_as_float(agv[0]);
            As[nb][lk + 1][lm] = __uint_as_float(agv[1]);
            As[nb][lk + 2][lm] = __uint_as_float(agv[2]);
            As[nb][lk + 3][lm] = __uint_as_float(agv[3]);
            float4 bs4;
            bs4.x = __uint_as_float(bgv[0]); bs4.y = __uint_as_float(bgv[1]);
            bs4.z = __uint_as_float(bgv[2]); bs4.w = __uint_as_float(bgv[3]);
            *(float4*)&Bs[nb][bkr][bn] = bs4;
            __syncthreads();
        }
    }

    float gate = 0.f, gate1 = 0.f;
    if (MODE == 1) {
        gate = 1.f / (1.f + __expf(-skipp[0]));
        gate1 = 1.f - gate;
    }
#pragma unroll
    for (int mt = 0; mt < 2; mt++) {
        const int r0 = m0 + wm * 32 + mt * 16 + lr;
        const int r1 = r0 + 8;
#pragma unroll
        for (int nt = 0; nt < 8; nt++) {
            const int col = n0 + wn * 64 + nt * 8 + lc * 2;
            float2 bv = *(const float2*)&bias[col];
            if (r0 < M) {
                float o0 = acc[mt][nt][0] + bv.x;
                float o1 = acc[mt][nt][1] + bv.y;
                float* Cp = C + (long)r0 * N + col;
                if (MODE == 1) {
                    const float* xo = xold + (long)r0 * N + col;
                    o0 = gate * o0 + gate1 * xo[0];
                    o1 = gate * o1 + gate1 * xo[1];
                }
                float2 st; st.x = o0; st.y = o1;
                *(float2*)Cp = st;
            }
            if (r1 < M) {
                float o0 = acc[mt][nt][2] + bv.x;
                float o1 = acc[mt][nt][3] + bv.y;
                float* Cp = C + (long)r1 * N + col;
                if (MODE == 1) {
                    const float* xo = xold + (long)r1 * N + col;
                    o0 = gate * o0 + gate1 * xo[0];
                    o1 = gate * o1 + gate1 * xo[1];
                }
                float2 st; st.x = o0; st.y = o1;
                *(float2*)Cp = st;
            }
        }
    }
}

// ---------------- q-tilde: qt[n,h,d] = (sum_f q[n,h,f]*arel[h,d,f]) * prel[h] * scale ----------
__global__ __launch_bounds__(128) void qt_kernel(
    const float* __restrict__ kqv_g, const float* __restrict__ kqv_d,
    const float* __restrict__ arel_l, const float* __restrict__ prel_l, float scale,
    float* __restrict__ qt_g0, float* __restrict__ qt_g2, float* __restrict__ qt_d)
{
    const float* kqv;
    const float* arel;
    const float* prel;
    float* qt;
    int Nn;
    if (blockIdx.y == 0)      { kqv = kqv_g; arel = arel_l;            prel = prel_l;     qt = qt_g0; Nn = NG; }
    else if (blockIdx.y == 1) { kqv = kqv_g; arel = arel_l + 2 * 4096; prel = prel_l + 8; qt = qt_g2; Nn = NG; }
    else                      { kqv = kqv_d; arel = arel_l + 1 * 4096; prel = prel_l + 4; qt = qt_d;  Nn = ND; }

    __shared__ float arelT[32][128]; // [f][h*32+d]
    __shared__ float qsh[128];
    const int t = threadIdx.x; // t = h*32+d
    for (int i = t; i < 4096; i += 128) {
        int h = i >> 10, rem = i & 1023;
        int d = rem >> 5, f = rem & 31;
        arelT[f][(h << 5) + d] = arel[i];
    }
    const int h = t >> 5;
    const float pr = prel[h] * scale;
    __syncthreads();
    for (int node = blockIdx.x; node < Nn; node += gridDim.x) {
        qsh[t] = kqv[(long)node * 384 + 128 + t]; // q block
        __syncthreads();
        float s = 0.f;
        const float* qh = &qsh[h << 5];
#pragma unroll
        for (int f = 0; f < 32; f++) s += qh[f] * arelT[f][t];
        qt[(long)node * 128 + t] = s * pr;
        __syncthreads();
    }
}

// ---------------- aggregation (both dst families in ONE launch) ----------------
__global__ __launch_bounds__(256) void agg2_kernel(
    const float* __restrict__ kqvA0, const float* __restrict__ kqvA1,
    const float* __restrict__ qtA0, const float* __restrict__ qtA1,
    const float* __restrict__ mrelA0, const float* __restrict__ mrelA1,
    const int* __restrict__ offA, const int* __restrict__ listA, float* __restrict__ aggA,
    int NA, int nblkA,
    const float* __restrict__ kqvB0, const float* __restrict__ qtB0,
    const float* __restrict__ mrelB0,
    const int* __restrict__ offB, const int* __restrict__ listB, float* __restrict__ aggB, int NB)
{
    __shared__ float mr0[4096];
    __shared__ float mr1[4096];
    __shared__ __align__(16) float Ssh[8][128];
    const float *kqv0, *kqv1, *qt0t, *qt1t, *mrel0g, *mrel1g;
    const int *off, *list;
    float* agg;
    int Ndst, two_types, bx;
    if ((int)blockIdx.x < nblkA) {
        kqv0 = kqvA0; kqv1 = kqvA1; qt0t = qtA0; qt1t = qtA1;
        mrel0g = mrelA0; mrel1g = mrelA1;
        off = offA; list = listA; agg = aggA; Ndst = NA; two_types = 1; bx = blockIdx.x;
    } else {
        kqv0 = kqvB0; kqv1 = kqvB0; qt0t = qtB0; qt1t = qtB0;
        mrel0g = mrelB0; mrel1g = mrelB0;
        off = offB; list = listB; agg = aggB; Ndst = NB; two_types = 0; bx = blockIdx.x - nblkA;
    }
    const int tid = threadIdx.x;
    for (int i = tid; i < 4096; i += 256) {
        mr0[i] = mrel0g[i];
        mr1[i] = mrel1g[i];
    }
    __syncthreads();
    const int warp = tid >> 5, lane = tid & 31;
    const int h = lane >> 3, f0 = (lane & 7) << 2;

    const int node = bx * 8 + warp;
    if (node >= Ndst) return;
    float4 q0 = ((const float4*)(qt0t + (long)node * 128))[lane];
    float4 q1 = make_float4(0.f, 0.f, 0.f, 0.f);
    if (two_types) q1 = ((const float4*)(qt1t + (long)node * 128))[lane];
    float m = -1e30f, lsum = 0.f;
    float4 S0 = make_float4(0.f, 0.f, 0.f, 0.f);
    float4 S1 = make_float4(0.f, 0.f, 0.f, 0.f);
    const int b = off[node], e = off[node + 1];
    for (int i = b; i < e; i++) {
        const int ent = list[i];
        const int tb = ent & 1;
        const float4* base = (const float4*)((tb ? kqv1 : kqv0) + (long)(ent >> 1) * 384);
        float4 k4 = base[lane];       // k block
        float4 qr = tb ? q1 : q0;
        float p = k4.x * qr.x + k4.y * qr.y + k4.z * qr.z + k4.w * qr.w;
        p += __shfl_xor_sync(0xffffffffu, p, 1);
        p += __shfl_xor_sync(0xffffffffu, p, 2);
        p += __shfl_xor_sync(0xffffffffu, p, 4);
        float mn = fmaxf(m, p);
        float c = __expf(m - mn);
        float ex = __expf(p - mn);
        m = mn;
        lsum = lsum * c + ex;
        float4 v4 = base[64 + lane];  // v block
        S0.x *= c; S0.y *= c; S0.z *= c; S0.w *= c;
        S1.x *= c; S1.y *= c; S1.z *= c; S1.w *= c;
        if (tb) { S1.x += ex * v4.x; S1.y += ex * v4.y; S1.z += ex * v4.z; S1.w += ex * v4.w; }
        else    { S0.x += ex * v4.x; S0.y += ex * v4.y; S0.z += ex * v4.z; S0.w += ex * v4.w; }
    }
    float inv = lsum > 0.f ? 1.f / lsum : 0.f;
    float4 o = make_float4(0.f, 0.f, 0.f, 0.f);
    ((float4*)Ssh[warp])[lane] = S0;
    __syncwarp();
    {
        const float* Sh = &Ssh[warp][h << 5];
        const float* Mm = &mr0[h << 10];
#pragma unroll
        for (int d = 0; d < 32; d++) {
            float s = Sh[d];
            const float* mp = Mm + (d << 5) + f0;
            o.x += s * mp[0]; o.y += s * mp[1]; o.z += s * mp[2]; o.w += s * mp[3];
        }
    }
    if (two_types) {
        __syncwarp();
        ((float4*)Ssh[warp])[lane] = S1;
        __syncwarp();
        const float* Sh = &Ssh[warp][h << 5];
        const float* Mm = &mr1[h << 10];
#pragma unroll
        for (int d = 0; d < 32; d++) {
            float s = Sh[d];
            const float* mp = Mm + (d << 5) + f0;
            o.x += s * mp[0]; o.y += s * mp[1]; o.z += s * mp[2]; o.w += s * mp[3];
        }
    }
    o.x *= inv; o.y *= inv; o.z *= inv; o.w *= inv;
    ((float4*)(agg + (long)node * 128))[lane] = o;
}

// ---------------- host ----------------
extern "C" void kernel_launch(void* const* d_in, const int* in_sizes, int n_in,
                              void* d_out, int out_size) {
    const float* x_d    = (const float*)d_in[0];
    const float* x_g    = (const float*)d_in[1];
    const int*   src_dg = (const int*)d_in[2];
    const int*   dst_dg = (const int*)d_in[3];
    const int*   src_gd = (const int*)d_in[4];
    const int*   dst_gd = (const int*)d_in[5];
    const int*   src_gg = (const int*)d_in[6];
    const int*   dst_gg = (const int*)d_in[7];
    const float* Wkqv_d = (const float*)d_in[8];
    const float* bkqv_d = (const float*)d_in[9];
    const float* Wkqv_g = (const float*)d_in[10];
    const float* bkqv_g = (const float*)d_in[11];
    const float* Wout_d = (const float*)d_in[12];
    const float* bout_d = (const float*)d_in[13];
    const float* Wout_g = (const float*)d_in[14];
    const float* bout_g = (const float*)d_in[15];
    const float* skip_d = (const float*)d_in[16];
    const float* skip_g = (const float*)d_in[17];
    const float* arel   = (const float*)d_in[18];
    const float* mrel   = (const float*)d_in[19];
    const float* prel   = (const float*)d_in[20];

    float *kqv_d, *kqv_g, *qt_d, *qt_g0, *qt_g2, *agg_d, *agg_g, *xbuf_d, *xbuf_g;
    int *cnt_g, *off_g, *cur_g, *list_g, *cnt_d, *off_d, *cur_d, *list_d;
    cudaGetSymbolAddress((void**)&kqv_d, g_kqv_d);
    cudaGetSymbolAddress((void**)&kqv_g, g_kqv_g);
    cudaGetSymbolAddress((void**)&qt_d, g_qt_d);
    cudaGetSymbolAddress((void**)&qt_g0, g_qt_g0);
    cudaGetSymbolAddress((void**)&qt_g2, g_qt_g2);
    cudaGetSymbolAddress((void**)&agg_d, g_agg_d);
    cudaGetSymbolAddress((void**)&agg_g, g_agg_g);
    cudaGetSymbolAddress((void**)&xbuf_d, g_x_d);
    cudaGetSymbolAddress((void**)&xbuf_g, g_x_g);
    cudaGetSymbolAddress((void**)&cnt_g, g_cnt_g);
    cudaGetSymbolAddress((void**)&off_g, g_off_g);
    cudaGetSymbolAddress((void**)&cur_g, g_cur_g);
    cudaGetSymbolAddress((void**)&list_g, g_list_g);
    cudaGetSymbolAddress((void**)&cnt_d, g_cnt_d);
    cudaGetSymbolAddress((void**)&off_d, g_off_d);
    cudaGetSymbolAddress((void**)&cur_d, g_cur_d);
    cudaGetSymbolAddress((void**)&list_d, g_list_d);

    // ---- CSR build ----
    cudaMemsetAsync(cnt_g, 0, sizeof(int) * NG);
    cudaMemsetAsync(cnt_d, 0, sizeof(int) * ND);
    hist_all<<<512, 256>>>(dst_dg, dst_gg, dst_gd, cnt_g, cnt_d);
    scan2_kernel<<<2, 1024>>>(cnt_g, off_g, cnt_d, off_d);
    cudaMemsetAsync(cur_g, 0, sizeof(int) * NG);
    cudaMemsetAsync(cur_d, 0, sizeof(int) * ND);
    fill_all<<<512, 256>>>(src_dg, dst_dg, src_gg, dst_gg, src_gd, dst_gd,
                           off_g, cur_g, list_g, off_d, cur_d, list_d);
    sort_all<<<(NG + ND + 255) / 256, 256>>>(off_g, list_g, off_d, list_d);

    const float SCALE = 0.1767766952966369f; // 1/sqrt(32)
    const int nbyd = (ND + 127) / 128;       // 79
    const int nbyg = (NG + 127) / 128;       // 235
    const int nblkg = (NG + 7) / 8;          // 3750
    const int nblkd = (ND + 7) / 8;          // 1250
    const float* xd = x_d;
    const float* xg = x_g;
    for (int l = 0; l < 2; l++) {
        // fused K/Q/V projections for both node types (one launch)
        gemm_tc<0><<<dim3(3, nbyd + nbyg), 256>>>(
            xd, Wkqv_d + l * 128 * 384, bkqv_d + l * 384, nullptr, nullptr, kqv_d, ND,
            xg, Wkqv_g + l * 128 * 384, bkqv_g + l * 384, nullptr, nullptr, kqv_g, NG,
            nbyd, 384);
        // dst-side q-tilde per (dst node, edge type)
        qt_kernel<<<dim3(512, 3), 128>>>(kqv_g, kqv_d, arel + l * 3 * 4096, prel + l * 12,
                                         SCALE, qt_g0, qt_g2, qt_d);
        // edge aggregation (both dst families, one launch)
        agg2_kernel<<<nblkg + nblkd, 256>>>(
            kqv_d, kqv_g, qt_g0, qt_g2,
            mrel + (l * 3 + 0) * 4096, mrel + (l * 3 + 2) * 4096,
            off_g, list_g, agg_g, NG, nblkg,
            kqv_g, qt_d, mrel + (l * 3 + 1) * 4096,
            off_d, list_d, agg_d, ND);
        // output projection + gated skip (both node types, one launch)
        float* od = (l == 1) ? (float*)d_out : xbuf_d;
        float* og = (l == 1) ? ((float*)d_out) + ND * HDIM : xbuf_g;
        gemm_tc<1><<<dim3(1, nbyd + nbyg), 256>>>(
            agg_d, Wout_d + l * 128 * 128, bout_d + l * 128, xd, skip_d + l, od, ND,
            agg_g, Wout_g + l * 128 * 128, bout_g + l * 128, xg, skip_g + l, og, NG,
            nbyd, 128);
        xd = od;
        xg = og;
    }
}

// round 13
// speedup vs baseline: 1.5800x; 1.3095x over previous
#include <cuda_runtime.h>
#include <math.h>
#include <stdint.h>

#define ND 10000
#define NG 30000
#define HDIM 128
#define EDG 150000
#define EGD 150000
#define EGG 300000
#define SCALEF 0.1767766952966369f

// ---------------- scratch (device globals; no allocation) ----------------
__device__ float g_kqv_d[ND * 384];
__device__ float g_kqv_g[NG * 512];
__device__ float g_agg_d[ND * HDIM];
__device__ float g_agg_g[NG * HDIM];
__device__ float g_x_d[ND * HDIM];
__device__ float g_x_g[NG * HDIM];
__device__ float g_Wg[2 * 128 * 512];
__device__ float g_bg[2 * 512];
__device__ float g_Wd[2 * 128 * 384];
__device__ float g_bd[2 * 384];
__device__ __align__(16) int g_cnt_g[NG + 1];
__device__ __align__(16) int g_off_g[NG + 1];
__device__ int g_cur_g[NG];
__device__ int g_list_g[EDG + EGG];
__device__ __align__(16) int g_cnt_d[ND + 1];
__device__ __align__(16) int g_off_d[ND + 1];
__device__ int g_cur_d[ND];
__device__ int g_list_d[EGD];

// ---------------- helpers ----------------
__device__ __forceinline__ float gelu_t(float x) {
    float u = 0.7978845608028654f * (x + 0.044715f * x * x * x);
    return 0.5f * x * (1.0f + tanhf(u));
}
__device__ __forceinline__ uint32_t f2tf32(float x) {
    uint32_t u;
    asm("cvt.rna.tf32.f32 %0, %1;" : "=r"(u) : "f"(x));
    return u;
}
__device__ __forceinline__ void mma_tf32(float* c, const uint32_t* a, uint32_t b0, uint32_t b1) {
    asm volatile(
        "mma.sync.aligned.m16n8k8.row.col.f32.tf32.tf32.f32 "
        "{%0,%1,%2,%3}, {%4,%5,%6,%7}, {%8,%9}, {%0,%1,%2,%3};"
        : "+f"(c[0]), "+f"(c[1]), "+f"(c[2]), "+f"(c[3])
        : "r"(a[0]), "r"(a[1]), "r"(a[2]), "r"(a[3]), "r"(b0), "r"(b1));
}

// ---------------- weight prep: fold arel/prel/scale into kqv weights ----------------
// builds per-layer fused W/b: g -> [k(128)|v(128)|qt_et0(128)|qt_et2(128)] N=512
//                             d -> [k(128)|v(128)|qt_et1(128)]            N=384
__global__ __launch_bounds__(256) void prep_weights(
    const float* __restrict__ Wkqv_d, const float* __restrict__ bkqv_d,
    const float* __restrict__ Wkqv_g, const float* __restrict__ bkqv_g,
    const float* __restrict__ arel, const float* __restrict__ prel,
    float* __restrict__ Wg, float* __restrict__ bg,
    float* __restrict__ Wd, float* __restrict__ bd)
{
    const int TOT = 2 * 129 * 896;
    for (int idx = blockIdx.x * blockDim.x + threadIdx.x; idx < TOT; idx += gridDim.x * blockDim.x) {
        int l = idx / (129 * 896);
        int rem = idx % (129 * 896);
        int row = rem / 896;
        int c = rem % 896;
        const float *Wsrc, *bsrc;
        float *dw, *db;
        int N, cc;
        bool is_g = c < 512;
        if (is_g) {
            cc = c; Wsrc = Wkqv_g + l * 128 * 384; bsrc = bkqv_g + l * 384;
            dw = Wg + l * 128 * 512; db = bg + l * 512; N = 512;
        } else {
            cc = c - 512; Wsrc = Wkqv_d + l * 128 * 384; bsrc = bkqv_d + l * 384;
            dw = Wd + l * 128 * 384; db = bd + l * 384; N = 384;
        }
        const bool isbias = (row == 128);
        float val;
        if (cc < 128) {
            val = isbias ? bsrc[cc] : Wsrc[row * 384 + cc];
        } else if (cc < 256) {
            int sc = 128 + cc;  // v block lives at cols 256..383 of source
            val = isbias ? bsrc[sc] : Wsrc[row * 384 + sc];
        } else {
            int et = is_g ? ((cc < 384) ? 0 : 2) : 1;
            int q = (cc - 256) & 127;
            int h = q >> 5, d = q & 31;
            const float* ar = arel + ((l * 3 + et) * 4 + h) * 1024 + d * 32;
            const float* wr = isbias ? (bsrc + 128 + h * 32) : (Wsrc + row * 384 + 128 + h * 32);
            float s = 0.f;
#pragma unroll
            for (int f = 0; f < 32; f++) s += wr[f] * ar[f];
            val = s * prel[(l * 3 + et) * 4 + h] * SCALEF;
        }
        if (isbias) db[cc] = val;
        else dw[row * N + cc] = val;
    }
}

// ---------------- CSR build ----------------
__global__ void hist_all(const int* __restrict__ dst_dg, const int* __restrict__ dst_gg,
                         const int* __restrict__ dst_gd, int* cnt_g, int* cnt_d) {
    const int NTOT = EDG + EGG + EGD;
    for (int i = blockIdx.x * blockDim.x + threadIdx.x; i < NTOT; i += gridDim.x * blockDim.x) {
        if (i < EDG) atomicAdd(&cnt_g[dst_dg[i]], 1);
        else if (i < EDG + EGG) atomicAdd(&cnt_g[dst_gg[i - EDG]], 1);
        else atomicAdd(&cnt_d[dst_gd[i - EDG - EGG]], 1);
    }
}

__global__ void scan2_kernel(const int* __restrict__ cnt_g, int* __restrict__ off_g,
                             const int* __restrict__ cnt_d, int* __restrict__ off_d) {
    const int* cnt = blockIdx.x == 0 ? cnt_g : cnt_d;
    int* off = blockIdx.x == 0 ? off_g : off_d;
    const int n = blockIdx.x == 0 ? NG : ND;
    __shared__ int part[1024];
    const int t = threadIdx.x;
    const int b = t * 32;
    int s = 0;
    if (b + 32 <= n) {
        const int4* p = (const int4*)(cnt + b);
#pragma unroll
        for (int i = 0; i < 8; i++) { int4 v = p[i]; s += v.x + v.y + v.z + v.w; }
    } else {
        for (int i = b; i < n; i++) s += cnt[i];
    }
    part[t] = s;
    __syncthreads();
    for (int d = 1; d < 1024; d <<= 1) {
        int v = 0;
        if (t >= d) v = part[t - d];
        __syncthreads();
        part[t] += v;
        __syncthreads();
    }
    int run = (t == 0) ? 0 : part[t - 1];
    int e = b + 32 < n ? b + 32 : n;
    for (int i = b; i < e; i++) { off[i] = run; run += cnt[i]; }
    if (b <= n && e == n) off[n] = run;
}

__global__ void fill_all(const int* __restrict__ src_dg, const int* __restrict__ dst_dg,
                         const int* __restrict__ src_gg, const int* __restrict__ dst_gg,
                         const int* __restrict__ src_gd, const int* __restrict__ dst_gd,
                         const int* __restrict__ off_g, int* cur_g, int* list_g,
                         const int* __restrict__ off_d, int* cur_d, int* list_d) {
    const int NTOT = EDG + EGG + EGD;
    for (int i = blockIdx.x * blockDim.x + threadIdx.x; i < NTOT; i += gridDim.x * blockDim.x) {
        if (i < EDG) {
            int d = dst_dg[i];
            int pos = off_g[d] + atomicAdd(&cur_g[d], 1);
            list_g[pos] = (src_dg[i] << 1);
        } else if (i < EDG + EGG) {
            int j = i - EDG;
            int d = dst_gg[j];
            int pos = off_g[d] + atomicAdd(&cur_g[d], 1);
            list_g[pos] = (src_gg[j] << 1) | 1;
        } else {
            int j = i - EDG - EGG;
            int d = dst_gd[j];
            int pos = off_d[d] + atomicAdd(&cur_d[d], 1);
            list_d[pos] = (src_gd[j] << 1);
        }
    }
}

#define SORT_CAP 48
__global__ __launch_bounds__(256) void sort_all(const int* __restrict__ off_g, int* list_g,
                                                const int* __restrict__ off_d, int* list_d) {
    __shared__ int sbuf[SORT_CAP * 256];
    int node = blockIdx.x * blockDim.x + threadIdx.x;
    const int t = threadIdx.x;
    const int* off;
    int* list;
    if (node < NG) { off = off_g; list = list_g; }
    else if (node < NG + ND) { off = off_d; list = list_d; node -= NG; }
    else return;
    const int b = off[node], e = off[node + 1];
    const int deg = e - b;
    if (deg <= 1) return;
    if (deg <= SORT_CAP) {
        for (int j = 0; j < deg; j++) sbuf[j * 256 + t] = list[b + j];
        for (int i = 1; i < deg; i++) {
            int v = sbuf[i * 256 + t];
            int j = i - 1;
            while (j >= 0 && sbuf[j * 256 + t] > v) { sbuf[(j + 1) * 256 + t] = sbuf[j * 256 + t]; j--; }
            sbuf[(j + 1) * 256 + t] = v;
        }
        for (int j = 0; j < deg; j++) list[b + j] = sbuf[j * 256 + t];
    } else {
        for (int i = b + 1; i < e; i++) {
            int v = list[i];
            int j = i - 1;
            while (j >= b && list[j] > v) { list[j + 1] = list[j]; j--; }
            list[j + 1] = v;
        }
    }
}

// ---------------- tensor-core GEMM: 128x128 tile, K=128, tf32 mma.sync ----------------
// TWO independent problems per grid (split on blockIdx.y), per-problem N / x-block count.
template <int MODE>
__global__ __launch_bounds__(256) void gemm_tc(
    const float* __restrict__ A0, const float* __restrict__ W0, const float* __restrict__ bias0,
    const float* __restrict__ x0, const float* __restrict__ s0p, float* __restrict__ C0,
    int M0, int N0v, int nbx0,
    const float* __restrict__ A1, const float* __restrict__ W1, const float* __restrict__ bias1,
    const float* __restrict__ x1, const float* __restrict__ s1p, float* __restrict__ C1,
    int M1, int N1v, int nbx1,
    int nby0)
{
    __shared__ __align__(16) float As[2][8][136];  // [k][m]
    __shared__ __align__(16) float Bs[2][8][136];  // [k][n]
    const float *A, *W, *bias, *xold, *skipp;
    float* C;
    int M, N, nbx;
    int by = blockIdx.y;
    if (by < nby0) { A = A0; W = W0; bias = bias0; xold = x0; skipp = s0p; C = C0; M = M0; N = N0v; nbx = nbx0; }
    else { by -= nby0; A = A1; W = W1; bias = bias1; xold = x1; skipp = s1p; C = C1; M = M1; N = N1v; nbx = nbx1; }
    if ((int)blockIdx.x >= nbx) return;

    const int tid = threadIdx.x;
    const int m0 = by * 128, n0 = blockIdx.x * 128;
    const int wid = tid >> 5, lane = tid & 31;
    const int wm = wid & 3, wn = wid >> 2;
    const int lr = lane >> 2, lc = lane & 3;

    const int lm = tid >> 1, lk = (tid & 1) << 2;
    const int bkr = tid >> 5, bn = (tid & 31) << 2;
    const int arow = m0 + lm;
    const bool avalid = arow < M;
    const float* Aptr = A + (long)arow * 128 + lk;
    const float* Wptr = W + (long)bkr * N + n0 + bn;

    float acc[2][8][4];
#pragma unroll
    for (int i = 0; i < 2; i++)
#pragma unroll
        for (int j = 0; j < 8; j++)
#pragma unroll
            for (int q = 0; q < 4; q++) acc[i][j][q] = 0.f;

    uint32_t agv[4], bgv[4];
    {
        float4 av = avalid ? *(const float4*)Aptr : make_float4(0.f, 0.f, 0.f, 0.f);
        if (MODE == 1) { av.x = gelu_t(av.x); av.y = gelu_t(av.y); av.z = gelu_t(av.z); av.w = gelu_t(av.w); }
        agv[0] = f2tf32(av.x); agv[1] = f2tf32(av.y); agv[2] = f2tf32(av.z); agv[3] = f2tf32(av.w);
        float4 bv = *(const float4*)Wptr;
        bgv[0] = f2tf32(bv.x); bgv[1] = f2tf32(bv.y); bgv[2] = f2tf32(bv.z); bgv[3] = f2tf32(bv.w);
        As[0][lk + 0][lm] = __uint_as_float(agv[0]);
        As[0][lk + 1][lm] = __uint_as_float(agv[1]);
        As[0][lk + 2][lm] = __uint_as_float(agv[2]);
        As[0][lk + 3][lm] = __uint_as_float(agv[3]);
        float4 bs4;
        bs4.x = __uint_as_float(bgv[0]); bs4.y = __uint_as_float(bgv[1]);
        bs4.z = __uint_as_float(bgv[2]); bs4.w = __uint_as_float(bgv[3]);
        *(float4*)&Bs[0][bkr][bn] = bs4;
    }
    __syncthreads();

    for (int c = 0; c < 16; ++c) {
        const int buf = c & 1;
        if (c < 15) {
            const int k0 = (c + 1) * 8;
            float4 av = avalid ? *(const float4*)(Aptr + k0) : make_float4(0.f, 0.f, 0.f, 0.f);
            if (MODE == 1) { av.x = gelu_t(av.x); av.y = gelu_t(av.y); av.z = gelu_t(av.z); av.w = gelu_t(av.w); }
            agv[0] = f2tf32(av.x); agv[1] = f2tf32(av.y); agv[2] = f2tf32(av.z); agv[3] = f2tf32(av.w);
            float4 bv = *(const float4*)(Wptr + (long)k0 * N);
            bgv[0] = f2tf32(bv.x); bgv[1] = f2tf32(bv.y); bgv[2] = f2tf32(bv.z); bgv[3] = f2tf32(bv.w);
        }
        uint32_t af[2][4];
        const int mb = wm * 32;
#pragma unroll
        for (int mt = 0; mt < 2; mt++) {
            const int mo = mb + mt * 16 + lr;
            af[mt][0] = __float_as_uint(As[buf][lc][mo]);
            af[mt][1] = __float_as_uint(As[buf][lc][mo + 8]);
            af[mt][2] = __float_as_uint(As[buf][lc + 4][mo]);
            af[mt][3] = __float_as_uint(As[buf][lc + 4][mo + 8]);
        }
#pragma unroll
        for (int nt = 0; nt < 8; nt++) {
            const int nb2 = wn * 64 + nt * 8 + lr;
            uint32_t b0 = __float_as_uint(Bs[buf][lc][nb2]);
            uint32_t b1 = __float_as_uint(Bs[buf][lc + 4][nb2]);
            mma_tf32(acc[0][nt], af[0], b0, b1);
            mma_tf32(acc[1][nt], af[1], b0, b1);
        }
        if (c < 15) {
            __syncthreads();
            const int nb = buf ^ 1;
            As[nb][lk + 0][lm] = __uint_as_float(agv[0]);
            As[nb][lk + 1][lm] = __uint_as_float(agv[1]);
            As[nb][lk + 2][lm] = __uint_as_float(agv[2]);
            As[nb][lk + 3][lm] = __uint_as_float(agv[3]);
            float4 bs4;
            bs4.x = __uint_as_float(bgv[0]); bs4.y = __uint_as_float(bgv[1]);
            bs4.z = __uint_as_float(bgv[2]); bs4.w = __uint_as_float(bgv[3]);
            *(float4*)&Bs[nb][bkr][bn] = bs4;
            __syncthreads();
        }
    }

    float gate = 0.f, gate1 = 0.f;
    if (MODE == 1) {
        gate = 1.f / (1.f + __expf(-skipp[0]));
        gate1 = 1.f - gate;
    }
#pragma unroll
    for (int mt = 0; mt < 2; mt++) {
        const int r0 = m0 + wm * 32 + mt * 16 + lr;
        const int r1 = r0 + 8;
#pragma unroll
        for (int nt = 0; nt < 8; nt++) {
            const int col = n0 + wn * 64 + nt * 8 + lc * 2;
            float2 bv = *(const float2*)&bias[col];
            if (r0 < M) {
                float o0 = acc[mt][nt][0] + bv.x;
                float o1 = acc[mt][nt][1] + bv.y;
                float* Cp = C + (long)r0 * N + col;
                if (MODE == 1) {
                    const float* xo = xold + (long)r0 * N + col;
                    o0 = gate * o0 + gate1 * xo[0];
                    o1 = gate * o1 + gate1 * xo[1];
                }
                float2 st; st.x = o0; st.y = o1;
                *(float2*)Cp = st;
            }
            if (r1 < M) {
                float o0 = acc[mt][nt][2] + bv.x;
                float o1 = acc[mt][nt][3] + bv.y;
                float* Cp = C + (long)r1 * N + col;
                if (MODE == 1) {
                    const float* xo = xold + (long)r1 * N + col;
                    o0 = gate * o0 + gate1 * xo[0];
                    o1 = gate * o1 + gate1 * xo[1];
                }
                float2 st; st.x = o0; st.y = o1;
                *(float2*)Cp = st;
            }
        }
    }
}

// ---------------- aggregation: warp/dst, softmax w/o max (logits tiny), unroll-2 --------
// kqv rows: g [k|v|qt0|qt2] stride 128 f4 ; d [k|v|qt1] stride 96 f4. k at f4 0..31, v 32..63.
__global__ __launch_bounds__(256) void agg2_kernel(
    const float* __restrict__ kqvd, const float* __restrict__ kqvg,
    const float* __restrict__ mrelA0, const float* __restrict__ mrelA1,
    const float* __restrict__ mrelB0,
    const int* __restrict__ offA, const int* __restrict__ listA, float* __restrict__ aggA,
    int NA, int nblkA,
    const int* __restrict__ offB, const int* __restrict__ listB, float* __restrict__ aggB, int NB)
{
    __shared__ float mr0[4096];
    __shared__ float mr1[4096];
    __shared__ __align__(16) float Ssh[8][128];
    const int tid = threadIdx.x;
    const bool probA = (int)blockIdx.x < nblkA;
    if (probA) {
        for (int i = tid; i < 4096; i += 256) { mr0[i] = mrelA0[i]; mr1[i] = mrelA1[i]; }
    } else {
        for (int i = tid; i < 4096; i += 256) mr0[i] = mrelB0[i];
    }
    __syncthreads();
    const int warp = tid >> 5, lane = tid & 31;
    const int h = lane >> 3, f0 = (lane & 7) << 2;
    const float4* kg4 = (const float4*)kqvg;
    const float4* kd4 = (const float4*)kqvd;

    const int bx = probA ? blockIdx.x : blockIdx.x - nblkA;
    const int Ndst = probA ? NA : NB;
    const int node = bx * 8 + warp;
    if (node >= Ndst) return;
    const int* off = probA ? offA : offB;
    const int* list = probA ? listA : listB;
    float* agg = probA ? aggA : aggB;
    const float4* t0 = probA ? kd4 : kg4;
    const float4* t1 = kg4;
    const long s0 = probA ? 96 : 128;
    const long s1 = 128;

    float4 q0, q1;
    if (probA) {
        q0 = kg4[(long)node * 128 + 64 + lane];
        q1 = kg4[(long)node * 128 + 96 + lane];
    } else {
        q0 = kd4[(long)node * 96 + 64 + lane];
        q1 = q0;
    }

    float lsum = 0.f;
    float4 S0 = make_float4(0.f, 0.f, 0.f, 0.f);
    float4 S1 = make_float4(0.f, 0.f, 0.f, 0.f);
    const int b = off[node], e = off[node + 1];
    int i = b;
    for (; i + 2 <= e; i += 2) {
        const int ent0 = list[i], ent1 = list[i + 1];
        const int tb0 = ent0 & 1, tb1 = ent1 & 1;
        const float4* p0b = (tb0 ? t1 : t0) + (long)(ent0 >> 1) * (tb0 ? s1 : s0);
        const float4* p1b = (tb1 ? t1 : t0) + (long)(ent1 >> 1) * (tb1 ? s1 : s0);
        float4 k0 = p0b[lane];
        float4 k1 = p1b[lane];
        float4 v0 = p0b[32 + lane];
        float4 v1 = p1b[32 + lane];
        float4 qa = tb0 ? q1 : q0;
        float4 qb = tb1 ? q1 : q0;
        float pa = k0.x * qa.x + k0.y * qa.y + k0.z * qa.z + k0.w * qa.w;
        float pb = k1.x * qb.x + k1.y * qb.y + k1.z * qb.z + k1.w * qb.w;
        pa += __shfl_xor_sync(0xffffffffu, pa, 1);
        pb += __shfl_xor_sync(0xffffffffu, pb, 1);
        pa += __shfl_xor_sync(0xffffffffu, pa, 2);
        pb += __shfl_xor_sync(0xffffffffu, pb, 2);
        pa += __shfl_xor_sync(0xffffffffu, pa, 4);
        pb += __shfl_xor_sync(0xffffffffu, pb, 4);
        float e0 = __expf(pa), e1 = __expf(pb);
        lsum += e0 + e1;
        if (tb0) { S1.x += e0 * v0.x; S1.y += e0 * v0.y; S1.z += e0 * v0.z; S1.w += e0 * v0.w; }
        else     { S0.x += e0 * v0.x; S0.y += e0 * v0.y; S0.z += e0 * v0.z; S0.w += e0 * v0.w; }
        if (tb1) { S1.x += e1 * v1.x; S1.y += e1 * v1.y; S1.z += e1 * v1.z; S1.w += e1 * v1.w; }
        else     { S0.x += e1 * v1.x; S0.y += e1 * v1.y; S0.z += e1 * v1.z; S0.w += e1 * v1.w; }
    }
    if (i < e) {
        const int ent0 = list[i];
        const int tb0 = ent0 & 1;
        const float4* p0b = (tb0 ? t1 : t0) + (long)(ent0 >> 1) * (tb0 ? s1 : s0);
        float4 k0 = p0b[lane];
        float4 v0 = p0b[32 + lane];
        float4 qa = tb0 ? q1 : q0;
        float pa = k0.x * qa.x + k0.y * qa.y + k0.z * qa.z + k0.w * qa.w;
        pa += __shfl_xor_sync(0xffffffffu, pa, 1);
        pa += __shfl_xor_sync(0xffffffffu, pa, 2);
        pa += __shfl_xor_sync(0xffffffffu, pa, 4);
        float e0 = __expf(pa);
        lsum += e0;
        if (tb0) { S1.x += e0 * v0.x; S1.y += e0 * v0.y; S1.z += e0 * v0.z; S1.w += e0 * v0.w; }
        else     { S0.x += e0 * v0.x; S0.y += e0 * v0.y; S0.z += e0 * v0.z; S0.w += e0 * v0.w; }
    }
    float inv = lsum > 0.f ? 1.f / lsum : 0.f;
    float4 o = make_float4(0.f, 0.f, 0.f, 0.f);
    ((float4*)Ssh[warp])[lane] = S0;
    __syncwarp();
    {
        const float* Sh = &Ssh[warp][h << 5];
        const float* Mm = &mr0[h << 10];
#pragma unroll
        for (int d = 0; d < 32; d++) {
            float s = Sh[d];
            const float* mp = Mm + (d << 5) + f0;
            o.x += s * mp[0]; o.y += s * mp[1]; o.z += s * mp[2]; o.w += s * mp[3];
        }
    }
    if (probA) {
        __syncwarp();
        ((float4*)Ssh[warp])[lane] = S1;
        __syncwarp();
        const float* Sh = &Ssh[warp][h << 5];
        const float* Mm = &mr1[h << 10];
#pragma unroll
        for (int d = 0; d < 32; d++) {
            float s = Sh[d];
            const float* mp = Mm + (d << 5) + f0;
            o.x += s * mp[0]; o.y += s * mp[1]; o.z += s * mp[2]; o.w += s * mp[3];
        }
    }
    o.x *= inv; o.y *= inv; o.z *= inv; o.w *= inv;
    ((float4*)(agg + (long)node * 128))[lane] = o;
}

// ---------------- host ----------------
extern "C" void kernel_launch(void* const* d_in, const int* in_sizes, int n_in,
                              void* d_out, int out_size) {
    const float* x_d    = (const float*)d_in[0];
    const float* x_g    = (const float*)d_in[1];
    const int*   src_dg = (const int*)d_in[2];
    const int*   dst_dg = (const int*)d_in[3];
    const int*   src_gd = (const int*)d_in[4];
    const int*   dst_gd = (const int*)d_in[5];
    const int*   src_gg = (const int*)d_in[6];
    const int*   dst_gg = (const int*)d_in[7];
    const float* Wkqv_d = (const float*)d_in[8];
    const float* bkqv_d = (const float*)d_in[9];
    const float* Wkqv_g = (const float*)d_in[10];
    const float* bkqv_g = (const float*)d_in[11];
    const float* Wout_d = (const float*)d_in[12];
    const float* bout_d = (const float*)d_in[13];
    const float* Wout_g = (const float*)d_in[14];
    const float* bout_g = (const float*)d_in[15];
    const float* skip_d = (const float*)d_in[16];
    const float* skip_g = (const float*)d_in[17];
    const float* arel   = (const float*)d_in[18];
    const float* mrel   = (const float*)d_in[19];
    const float* prel   = (const float*)d_in[20];

    float *kqv_d, *kqv_g, *agg_d, *agg_g, *xbuf_d, *xbuf_g, *Wg_, *bg_, *Wd_, *bd_;
    int *cnt_g, *off_g, *cur_g, *list_g, *cnt_d, *off_d, *cur_d, *list_d;
    cudaGetSymbolAddress((void**)&kqv_d, g_kqv_d);
    cudaGetSymbolAddress((void**)&kqv_g, g_kqv_g);
    cudaGetSymbolAddress((void**)&agg_d, g_agg_d);
    cudaGetSymbolAddress((void**)&agg_g, g_agg_g);
    cudaGetSymbolAddress((void**)&xbuf_d, g_x_d);
    cudaGetSymbolAddress((void**)&xbuf_g, g_x_g);
    cudaGetSymbolAddress((void**)&Wg_, g_Wg);
    cudaGetSymbolAddress((void**)&bg_, g_bg);
    cudaGetSymbolAddress((void**)&Wd_, g_Wd);
    cudaGetSymbolAddress((void**)&bd_, g_bd);
    cudaGetSymbolAddress((void**)&cnt_g, g_cnt_g);
    cudaGetSymbolAddress((void**)&off_g, g_off_g);
    cudaGetSymbolAddress((void**)&cur_g, g_cur_g);
    cudaGetSymbolAddress((void**)&list_g, g_list_g);
    cudaGetSymbolAddress((void**)&cnt_d, g_cnt_d);
    cudaGetSymbolAddress((void**)&off_d, g_off_d);
    cudaGetSymbolAddress((void**)&cur_d, g_cur_d);
    cudaGetSymbolAddress((void**)&list_d, g_list_d);

    // ---- weight prep + CSR build ----
    prep_weights<<<904, 256>>>(Wkqv_d, bkqv_d, Wkqv_g, bkqv_g, arel, prel, Wg_, bg_, Wd_, bd_);
    cudaMemsetAsync(cnt_g, 0, sizeof(int) * NG);
    cudaMemsetAsync(cnt_d, 0, sizeof(int) * ND);
    hist_all<<<512, 256>>>(dst_dg, dst_gg, dst_gd, cnt_g, cnt_d);
    scan2_kernel<<<2, 1024>>>(cnt_g, off_g, cnt_d, off_d);
    cudaMemsetAsync(cur_g, 0, sizeof(int) * NG);
    cudaMemsetAsync(cur_d, 0, sizeof(int) * ND);
    fill_all<<<512, 256>>>(src_dg, dst_dg, src_gg, dst_gg, src_gd, dst_gd,
                           off_g, cur_g, list_g, off_d, cur_d, list_d);
    sort_all<<<(NG + ND + 255) / 256, 256>>>(off_g, list_g, off_d, list_d);

    const int nbyd = (ND + 127) / 128;  // 79
    const int nbyg = (NG + 127) / 128;  // 235
    const int nblkg = (NG + 7) / 8;     // 3750
    const int nblkd = (ND + 7) / 8;     // 1250
    const float* xd = x_d;
    const float* xg = x_g;
    for (int l = 0; l < 2; l++) {
        // fused K/V/q-tilde projections for both node types (one launch)
        gemm_tc<0><<<dim3(4, nbyd + nbyg), 256>>>(
            xd, Wd_ + l * 128 * 384, bd_ + l * 384, nullptr, nullptr, kqv_d, ND, 384, 3,
            xg, Wg_ + l * 128 * 512, bg_ + l * 512, nullptr, nullptr, kqv_g, NG, 512, 4,
            nbyd);
        // edge aggregation (both dst families, one launch)
        agg2_kernel<<<nblkg + nblkd, 256>>>(
            kqv_d, kqv_g,
            mrel + (l * 3 + 0) * 4096, mrel + (l * 3 + 2) * 4096, mrel + (l * 3 + 1) * 4096,
            off_g, list_g, agg_g, NG, nblkg,
            off_d, list_d, agg_d, ND);
        // output projection + gated skip (both node types, one launch)
        float* od = (l == 1) ? (float*)d_out : xbuf_d;
        float* og = (l == 1) ? ((float*)d_out) + ND * HDIM : xbuf_g;
        gemm_tc<1><<<dim3(1, nbyd + nbyg), 256>>>(
            agg_d, Wout_d + l * 128 * 128, bout_d + l * 128, xd, skip_d + l, od, ND, 128, 1,
            agg_g, Wout_g + l * 128 * 128, bout_g + l * 128, xg, skip_g + l, og, NG, 128, 1,
            nbyd);
        xd = od;
        xg = og;
    }
}